// round 9
// baseline (speedup 1.0000x reference)
#include <cuda_runtime.h>

// Normalized correlation layer, GB300 sm_103a — round 9.
// Identity: sum((a-ma)(b-mb))/(sa*sb) = (S_ab - 25*ma*mb) * (1/sa)*(1/sb).
//
// Round-9 vs round-8 (structure identical: 768 thr = 64c x 6jj x 2th, PB
// pair slab, staged coalesced flush):
//  - WARP REMAP: warp = 16 channels x 2 jj (was 32 channels). pb/a1f/stat
//    smem loads now touch only 128B distinct per warp-op (jj-halves
//    broadcast-share) -> crossbar cost of the dominant pb stream HALVES.
//    Round-8 arithmetic: crossbar ~16K cyc/CTA (L1 52%) was the binder.
//  - A1F c-stride padded to 80 floats so jj-halves hit disjoint banks.
//  - B-stats staged to smem at fill (epilogue LDS, not tail LDG).
//  - flush indexing without integer division.

#define NB 16
#define NR 37

typedef unsigned long long u64;

__device__ __forceinline__ u64 fma2_(u64 a, u64 b, u64 c) {
    u64 d; asm("fma.rn.f32x2 %0, %1, %2, %3;" : "=l"(d) : "l"(a), "l"(b), "l"(c)); return d;
}
__device__ __forceinline__ u64 mul2_(u64 a, u64 b) {
    u64 d; asm("mul.rn.f32x2 %0, %1, %2;" : "=l"(d) : "l"(a), "l"(b)); return d;
}
__device__ __forceinline__ u64 add2_(u64 a, u64 b) {
    u64 d; asm("add.rn.f32x2 %0, %1, %2;" : "=l"(d) : "l"(a), "l"(b)); return d;
}
__device__ __forceinline__ u64 pk2(float x, float y) {
    u64 r; asm("mov.b64 %0, {%1, %2};" : "=l"(r) : "f"(x), "f"(y)); return r;
}
__device__ __forceinline__ float2 upk2(u64 v) {
    float2 f; asm("mov.b64 {%0, %1}, %2;" : "=f"(f.x), "=f"(f.y) : "l"(v)); return f;
}

// Stats. g_nA = -25*mean1, g_rA = rstd1, layout [b][37][j][ch].
// Image2 stats w-pair packed, u64[b][39][t][ch].
__device__ float  g_nA [NB * NR * 12 * 128];
__device__ float  g_rA [NB * NR * 12 * 128];
__device__ float2 g_mBt[NB * 39 * 6 * 128];
__device__ float2 g_rBt[NB * 39 * 6 * 128];

// ---------------------------------------------------------------------------
// Pass 1: per-patch per-channel mean and rstd (unchanged).
// ---------------------------------------------------------------------------
__global__ __launch_bounds__(384) void nc_stats_kernel(
    const float* __restrict__ in1, const float* __restrict__ in2)
{
    __shared__ u64 slab[5 * 16 * 64];
    const int bx  = blockIdx.x;
    const int b   = blockIdx.y;
    const int tid = threadIdx.x;

    const bool img1 = bx < NR;
    const int  st   = img1 ? bx : bx - NR;
    const int  roff = img1 ? 2 : 4;
    const u64* inv  = (const u64*)(img1 ? in1 : in2);

    for (int i = tid; i < 5 * 16 * 64; i += 384) {
        int c = i & 63, col = (i >> 6) & 15, dr = i >> 10;
        int row = st + dr - roff;
        int cg  = col - 2;
        u64 v = 0ull;
        if ((unsigned)row < 37u && (unsigned)cg < 12u)
            v = inv[((b * 37 + row) * 12 + cg) * 64 + c];
        slab[i] = v;
    }
    __syncthreads();

    for (int t = tid; t < 12 * 64; t += 384) {
        int j = t >> 6, c = t & 63;
        u64 s = 0ull, q = 0ull;
        #pragma unroll
        for (int dr = 0; dr < 5; dr++) {
            #pragma unroll
            for (int dc = 0; dc < 5; dc++) {
                u64 v = slab[(dr * 16 + j + dc) * 64 + c];
                s = add2_(s, v);
                q = fma2_(v, v, q);
            }
        }
        float2 sf = upk2(s), qf = upk2(q);
        float mx = sf.x * 0.04f, my = sf.y * 0.04f;
        float vx = qf.x * 0.04f - mx * mx;
        float vy = qf.y * 0.04f - my * my;
        float rx = rsqrtf(vx), ry = rsqrtf(vy);

        if (img1) {
            int idx = ((b * 37 + st) * 12 + j) * 128 + 2 * c;
            g_nA[idx]     = -25.0f * mx;
            g_nA[idx + 1] = -25.0f * my;
            g_rA[idx]     = rx;
            g_rA[idx + 1] = ry;
        } else {
            float* mB = (float*)g_mBt;
            float* rB = (float*)g_rBt;
            int base = (((b * 39 + st) * 6 + (j >> 1)) * 128) * 2 + (j & 1);
            mB[base + 4 * c]     = mx;
            mB[base + 4 * c + 2] = my;
            rB[base + 4 * c]     = rx;
            rB[base + 4 * c + 2] = ry;
        }
    }
}

// ---------------------------------------------------------------------------
// Pass 2. Smem offsets (bytes).
// ---------------------------------------------------------------------------
#define PB_OFF     0                        // u64[9][15][64]         69120 B
#define A1F_OFF    69120                    // f32[5][16][80]         25600 B
#define SBM_OFF    94720                    // u64[5][6][64]          15360 B
#define SBR_OFF    110080                   // u64[5][6][64]          15360 B
#define STAGE_OFF  125440                   // f32[6][3848]           92352 B
#define STAGE_ROW  3848
#define SMEM_BYTES 217792

__global__ __launch_bounds__(768, 1) void nc_corr_kernel(
    const float* __restrict__ in1, const float* __restrict__ in2,
    float* __restrict__ out)
{
    extern __shared__ char smraw[];
    u64*   PB    = (u64*)smraw;
    float* A1F   = (float*)(smraw + A1F_OFF);
    u64*   SBM   = (u64*)(smraw + SBM_OFF);
    u64*   SBR   = (u64*)(smraw + SBR_OFF);
    float* stage = (float*)(smraw + STAGE_OFF);

    const int r   = blockIdx.x;
    const int b   = blockIdx.y;
    const int chv = blockIdx.z;

    const int tid  = threadIdx.x;
    // Warp remap: warp w = th*12 + jjp*4 + cq ; lane = jj01*16 + lc.
    const int w    = tid >> 5;
    const int lane = tid & 31;
    const int th   = w / 12;           // 0..1
    const int jjp  = (w % 12) >> 2;    // 0..2
    const int cq   = w & 3;            // 0..3
    const int jj01 = lane >> 4;        // 0..1
    const int lc   = lane & 15;        // 0..15
    const int c    = cq * 16 + lc;     // 0..63
    const int jj   = jjp * 2 + jj01;   // 0..5
    const int ch   = chv * 64 + c;

    // ---- fills (linear tid, independent of compute mapping) ----
    // PB[row][x][c] = (A2pad[x], A2pad[x+1]) for pad2 row r+row.
    for (int i = tid; i < 9 * 15 * 64; i += 768) {
        int cc = i & 63, x = (i >> 6) % 15, row = i / (15 * 64);
        int irow = r + row - 4;
        float vlo = 0.f, vhi = 0.f;
        if ((unsigned)irow < 37u) {
            const float* base = in2 + ((b * 37 + irow) * 12) * 128 + chv * 64 + cc;
            int collo = x - 2, colhi = x - 1;
            if ((unsigned)collo < 12u) vlo = base[collo * 128];
            if ((unsigned)colhi < 12u) vhi = base[colhi * 128];
        }
        PB[i] = pk2(vlo, vhi);
    }
    // A1F[dr][col][c-pad80] = scalar f32 image1 value, pad1 row r+dr.
    for (int i = tid; i < 5 * 16 * 64; i += 768) {
        int cc = i & 63, col = (i >> 6) & 15, dr = i >> 10;
        int irow = r + dr - 2, icol = col - 2;
        float v = 0.f;
        if ((unsigned)irow < 37u && (unsigned)icol < 12u)
            v = in1[((b * 37 + irow) * 12 + icol) * 128 + chv * 64 + cc];
        A1F[(dr * 16 + col) * 80 + cc] = v;
    }
    // B-stats slabs: slot s holds row-start (r+s <= 38 ? r+s : r+s-2).
    for (int i = tid; i < 5 * 6 * 64; i += 768) {
        int cc = i & 63, t = (i >> 6) % 6, s = i / (6 * 64);
        int rs = r + s; if (rs > 38) rs -= 2;
        int gi = ((b * 39 + rs) * 6 + t) * 128 + chv * 64 + cc;
        SBM[i] = ((const u64*)g_mBt)[gi];
        SBR[i] = ((const u64*)g_rBt)[gi];
    }
    __syncthreads();

    #pragma unroll 1
    for (int ph = 0; ph < 2; ph++) {
        const int j = jj + 6 * ph;

        float a1f[5][5];
        u64 acc[5][3];
        #pragma unroll
        for (int d = 0; d < 5; d++)
            #pragma unroll
            for (int tt = 0; tt < 3; tt++) acc[d][tt] = 0ull;

        // Fully static rho loop: dr = rho - d compile-time; pb batches of 9
        // LDS.64 that cost 1 crossbar cycle each (128B distinct, jj-broadcast).
        #pragma unroll
        for (int rho = 0; rho < 9; rho++) {
            if (rho < 5) {
                #pragma unroll
                for (int dc = 0; dc < 5; dc++)
                    a1f[rho][dc] = A1F[(rho * 16 + j + dc) * 80 + c];
            }
            u64 pb[9];
            #pragma unroll
            for (int k = 0; k < 9; k++)
                pb[k] = PB[(rho * 15 + 6 * th + k) * 64 + c];

            #pragma unroll
            for (int d = 0; d < 5; d++) {
                const int dr = rho - d;                 // compile-time
                if (dr >= 0 && dr < 5) {
                    #pragma unroll
                    for (int dc = 0; dc < 5; dc++) {
                        const u64 a = pk2(a1f[dr][dc], a1f[dr][dc]);
                        #pragma unroll
                        for (int tt = 0; tt < 3; tt++)
                            acc[d][tt] = fma2_(a, pb[2 * tt + dc], acc[d][tt]);
                    }
                }
            }
        }

        // Epilogue. Stats from smem slot d (clamped row folded into fill).
        // row2 duplication (r=35,36): d>=3 clamped -> result equals d-2.
        const int giA = ((b * 37 + r) * 12 + j) * 128 + ch;
        const float na = g_nA[giA];
        const float ra = g_rA[giA];
        const u64 na2 = pk2(na, na);
        const u64 ra2 = pk2(ra, ra);
        float* srow = stage + jj * STAGE_ROW + c * 60 + 6 * th;

        #pragma unroll
        for (int d = 0; d < 5; d++) {
            const bool clamp = (d >= 3) && (r + d > 38);
            const int sbase = (d * 6 + 3 * th) * 64 + c;
            #pragma unroll
            for (int tt = 0; tt < 3; tt++) {
                u64 s = acc[d][tt];
                if (d >= 3) s = clamp ? acc[d - 2][tt] : s;
                u64 mbp = SBM[sbase + tt * 64];
                u64 rbp = SBR[sbase + tt * 64];
                u64 res = mul2_(fma2_(na2, mbp, s), mul2_(ra2, rbp));
                *(u64*)(srow + 12 * d + 2 * tt) = res;
            }
        }
        __syncthreads();

        // Coalesced flush, no division: per j-tile 960 float4 (0..767 all,
        // 768..959 by tid<192).
        {
            float* obase = out + ((b * 37 + r) * 12 + 6 * ph) * 7680 + chv * 3840;
            #pragma unroll 1
            for (int jl = 0; jl < 6; jl++) {
                const float* st0 = stage + jl * STAGE_ROW;
                float* og = obase + jl * 7680;
                *(float4*)(og + tid * 4) = *(const float4*)(st0 + tid * 4);
                if (tid < 192)
                    *(float4*)(og + (768 + tid) * 4) =
                        *(const float4*)(st0 + (768 + tid) * 4);
            }
        }
        __syncthreads();
    }
}

// ---------------------------------------------------------------------------
extern "C" void kernel_launch(void* const* d_in, const int* in_sizes, int n_in,
                              void* d_out, int out_size)
{
    const float* in1 = (const float*)d_in[0];
    const float* in2 = (const float*)d_in[1];
    float* out = (float*)d_out;

    cudaFuncSetAttribute(nc_corr_kernel,
                         cudaFuncAttributeMaxDynamicSharedMemorySize, SMEM_BYTES);

    nc_stats_kernel<<<dim3(NR + 39, NB), 384>>>(in1, in2);
    nc_corr_kernel<<<dim3(NR, NB, 2), 768, SMEM_BYTES>>>(in1, in2, out);
}